// round 1
// baseline (speedup 1.0000x reference)
#include <cuda_runtime.h>
#include <math.h>

// Problem constants
#define BB   8
#define CQ   1024
#define CR   512
#define HID  256
#define NP   2304          // H*W = 48*48

// Scratch in device globals (no allocation allowed in kernel_launch)
__device__ float g_Q[(size_t)BB * NP * HID];        // [b][i][k]  18.9 MB
__device__ float g_K[(size_t)BB * NP * HID];        // [b][p][k]  18.9 MB
__device__ float g_attn[(size_t)BB * NP * NP];      // [b][p][i] 169.9 MB (transposed logits)

// ---------------------------------------------------------------------------
// Generic 128x128x8 fp32 GEMM, 256 threads, 8x8 per-thread microtile.
//   C[m][n] = sum_k A'[m][k] * B'[k][n]  (+ bias[n])
// TA=false: A is stored [k][m] (m fast, lda = row stride along k)  -> direct load
// TA=true : A is stored [m][k] (k fast, lda = row stride along m)  -> transposed load
// Same for TB on the B operand (B'[k][n]).
// All dims assumed multiples of tile sizes (true for this problem).
// ---------------------------------------------------------------------------
template<bool TA, bool TB, bool BIAS>
__global__ void __launch_bounds__(256) gemm128(
    const float* __restrict__ A, int lda, size_t sA,
    const float* __restrict__ B, int ldb, size_t sB,
    const float* __restrict__ bias,
    float* __restrict__ C, int ldc, size_t sC,
    int Ktot)
{
    constexpr int SPAD = 132;               // padded row to dodge bank conflicts
    __shared__ float As[8 * SPAD];
    __shared__ float Bs[8 * SPAD];

    const int bz  = blockIdx.z;
    A += sA * bz; B += sB * bz; C += sC * bz;

    const int tid = threadIdx.x;
    const int m0  = blockIdx.x * 128;
    const int n0  = blockIdx.y * 128;

    // direct-mode load indices: [k-row 0..7][col, float4]
    const int drow = tid >> 5;              // 0..7
    const int dcol = (tid & 31) * 4;        // 0..124
    // transpose-mode load indices: [row 0..127][k-seg 0/4]
    const int trow = tid >> 1;              // 0..127
    const int tseg = (tid & 1) * 4;         // 0 or 4

    const float* Aptr = TA ? (A + (size_t)(m0 + trow) * lda + tseg)
                           : (A + (size_t)drow * lda + m0 + dcol);
    const float* Bptr = TB ? (B + (size_t)(n0 + trow) * ldb + tseg)
                           : (B + (size_t)drow * ldb + n0 + dcol);
    const size_t astep = TA ? 8 : (size_t)8 * lda;
    const size_t bstep = TB ? 8 : (size_t)8 * ldb;

    const int tx = tid & 15;                // n-direction
    const int ty = tid >> 4;                // m-direction

    float acc[8][8];
    #pragma unroll
    for (int i = 0; i < 8; i++)
        #pragma unroll
        for (int j = 0; j < 8; j++) acc[i][j] = 0.f;

    for (int k0 = 0; k0 < Ktot; k0 += 8) {
        float4 av = *(const float4*)Aptr;  Aptr += astep;
        float4 bv = *(const float4*)Bptr;  Bptr += bstep;

        __syncthreads();
        if (TA) {
            As[(tseg + 0) * SPAD + trow] = av.x;
            As[(tseg + 1) * SPAD + trow] = av.y;
            As[(tseg + 2) * SPAD + trow] = av.z;
            As[(tseg + 3) * SPAD + trow] = av.w;
        } else {
            *(float4*)&As[drow * SPAD + dcol] = av;
        }
        if (TB) {
            Bs[(tseg + 0) * SPAD + trow] = bv.x;
            Bs[(tseg + 1) * SPAD + trow] = bv.y;
            Bs[(tseg + 2) * SPAD + trow] = bv.z;
            Bs[(tseg + 3) * SPAD + trow] = bv.w;
        } else {
            *(float4*)&Bs[drow * SPAD + dcol] = bv;
        }
        __syncthreads();

        #pragma unroll
        for (int k = 0; k < 8; k++) {
            float a[8], b[8];
            *(float4*)&a[0] = *(const float4*)&As[k * SPAD + ty * 4];
            *(float4*)&a[4] = *(const float4*)&As[k * SPAD + 64 + ty * 4];
            *(float4*)&b[0] = *(const float4*)&Bs[k * SPAD + tx * 4];
            *(float4*)&b[4] = *(const float4*)&Bs[k * SPAD + 64 + tx * 4];
            #pragma unroll
            for (int mi = 0; mi < 8; mi++)
                #pragma unroll
                for (int ni = 0; ni < 8; ni++)
                    acc[mi][ni] = fmaf(a[mi], b[ni], acc[mi][ni]);
        }
    }

    // epilogue: two 4-row halves x two 4-col halves, float4 stores
    #pragma unroll
    for (int hm = 0; hm < 2; hm++) {
        #pragma unroll
        for (int j = 0; j < 4; j++) {
            const int m = m0 + hm * 64 + ty * 4 + j;
            #pragma unroll
            for (int hn = 0; hn < 2; hn++) {
                const int n = n0 + hn * 64 + tx * 4;
                float4 v;
                v.x = acc[hm * 4 + j][hn * 4 + 0];
                v.y = acc[hm * 4 + j][hn * 4 + 1];
                v.z = acc[hm * 4 + j][hn * 4 + 2];
                v.w = acc[hm * 4 + j][hn * 4 + 3];
                if (BIAS) {
                    v.x += bias[n + 0];
                    v.y += bias[n + 1];
                    v.z += bias[n + 2];
                    v.w += bias[n + 3];
                }
                *(float4*)&C[(size_t)m * ldc + n] = v;
            }
        }
    }
}

// ---------------------------------------------------------------------------
// Column-wise softmax over p on attnT[b][p][i]  (softmax axis = p = rows).
// One thread per query pixel i; fully coalesced along i.
// Online max/sum pass + normalize pass: 2 reads + 1 write of the 170MB tensor.
// ---------------------------------------------------------------------------
__global__ void __launch_bounds__(256) softmax_kernel(float* __restrict__ attn)
{
    const int b = blockIdx.y;
    const int i = blockIdx.x * 256 + threadIdx.x;
    float* col = attn + (size_t)b * NP * NP + i;

    float m = -3.402823466e38f;
    float s = 0.f;
    #pragma unroll 8
    for (int p = 0; p < NP; p++) {
        const float x = col[(size_t)p * NP];
        const float mn = fmaxf(m, x);
        s = s * __expf(m - mn) + __expf(x - mn);
        m = mn;
    }
    const float inv = 1.0f / s;
    #pragma unroll 8
    for (int p = 0; p < NP; p++) {
        const float x = col[(size_t)p * NP];
        col[(size_t)p * NP] = __expf(x - m) * inv;
    }
}

// ---------------------------------------------------------------------------
extern "C" void kernel_launch(void* const* d_in, const int* in_sizes, int n_in,
                              void* d_out, int out_size)
{
    const float* qf = (const float*)d_in[0];   // [B, CQ, 48, 48]
    const float* rf = (const float*)d_in[1];   // [B, CR, 48, 48]
    const float* Wq = (const float*)d_in[2];   // [HID, CQ]
    const float* bq = (const float*)d_in[3];   // [HID]
    const float* Wk = (const float*)d_in[4];   // [HID, CR]
    const float* bk = (const float*)d_in[5];   // [HID]
    float* out = (float*)d_out;                // [B, CR, 48, 48]

    float *Qp, *Kp, *Ap;
    cudaGetSymbolAddress((void**)&Qp, g_Q);
    cudaGetSymbolAddress((void**)&Kp, g_K);
    cudaGetSymbolAddress((void**)&Ap, g_attn);

    // 1) Q = Wq * qf + bq   -> g_Q[b][i][k]
    //    C[i][o] = sum_c qf[c][i] * Wq[o][c] + bq[o]
    gemm128<false, true, true><<<dim3(NP / 128, HID / 128, BB), 256>>>(
        qf, NP, (size_t)CQ * NP,
        Wq, CQ, 0,
        bq,
        Qp, HID, (size_t)NP * HID,
        CQ);

    // 2) K = Wk * rf + bk   -> g_K[b][p][k]
    gemm128<false, true, true><<<dim3(NP / 128, HID / 128, BB), 256>>>(
        rf, NP, (size_t)CR * NP,
        Wk, CR, 0,
        bk,
        Kp, HID, (size_t)NP * HID,
        CR);

    // 3) logits (transposed): attnT[p][i] = sum_k K[p][k] * Q[i][k]
    gemm128<true, true, false><<<dim3(NP / 128, NP / 128, BB), 256>>>(
        Kp, HID, (size_t)NP * HID,
        Qp, HID, (size_t)NP * HID,
        nullptr,
        Ap, NP, (size_t)NP * NP,
        HID);

    // 4) softmax over p (rows of attnT), per query pixel i
    softmax_kernel<<<dim3(NP / 256, BB), 256>>>(Ap);

    // 5) attended: out[c][i] = sum_p rf[c][p] * attnT[p][i]
    gemm128<true, false, false><<<dim3(CR / 128, NP / 128, BB), 256>>>(
        rf, NP, (size_t)CR * NP,
        Ap, NP, (size_t)NP * NP,
        nullptr,
        out, NP, (size_t)CR * NP,
        NP);
}

// round 2
// speedup vs baseline: 1.1892x; 1.1892x over previous
#include <cuda_runtime.h>
#include <math.h>

// Problem constants
#define BB   8
#define CQ   1024
#define CR   512
#define HID  256
#define NP   2304          // H*W = 48*48

// Scratch in device globals (no allocation allowed in kernel_launch)
__device__ float g_Q[(size_t)BB * NP * HID];        // [b][i][k]  18.9 MB
__device__ float g_K[(size_t)BB * NP * HID];        // [b][p][k]  18.9 MB
__device__ float g_attn[(size_t)BB * NP * NP];      // [b][p][i] 169.9 MB (transposed logits)

// ---------------------------------------------------------------------------
// Generic 128x128x8 fp32 GEMM, 256 threads, 8x8 per-thread microtile,
// double-buffered shared memory (1 barrier per k-step, load/compute overlap).
//   C[m][n] = sum_k A'[m][k] * B'[k][n]  (+ bias[n])
// TA=false: A is stored [k][m] (m fast)  -> direct float4 load
// TA=true : A is stored [m][k] (k fast)  -> transposed load
// ---------------------------------------------------------------------------
template<bool TA, bool TB, bool BIAS>
__global__ void __launch_bounds__(256) gemm128(
    const float* __restrict__ A, int lda, size_t sA,
    const float* __restrict__ B, int ldb, size_t sB,
    const float* __restrict__ bias,
    float* __restrict__ C, int ldc, size_t sC,
    int Ktot)
{
    constexpr int SPAD = 132;               // padded row to dodge bank conflicts
    __shared__ float As[2][8 * SPAD];
    __shared__ float Bs[2][8 * SPAD];

    const int bz  = blockIdx.z;
    A += sA * bz; B += sB * bz; C += sC * bz;

    const int tid = threadIdx.x;
    const int m0  = blockIdx.x * 128;
    const int n0  = blockIdx.y * 128;

    // direct-mode load indices: [k-row 0..7][col, float4]
    const int drow = tid >> 5;              // 0..7
    const int dcol = (tid & 31) * 4;        // 0..124
    // transpose-mode load indices: [row 0..127][k-seg 0/4]
    const int trow = tid >> 1;              // 0..127
    const int tseg = (tid & 1) * 4;         // 0 or 4

    const float* Aptr = TA ? (A + (size_t)(m0 + trow) * lda + tseg)
                           : (A + (size_t)drow * lda + m0 + dcol);
    const float* Bptr = TB ? (B + (size_t)(n0 + trow) * ldb + tseg)
                           : (B + (size_t)drow * ldb + n0 + dcol);
    const size_t astep = TA ? 8 : (size_t)8 * lda;
    const size_t bstep = TB ? 8 : (size_t)8 * ldb;

    const int tx = tid & 15;                // n-direction
    const int ty = tid >> 4;                // m-direction

    float acc[8][8];
    #pragma unroll
    for (int i = 0; i < 8; i++)
        #pragma unroll
        for (int j = 0; j < 8; j++) acc[i][j] = 0.f;

    // ---- prologue: load k-tile 0 into buffer 0 ----
    {
        float4 av = *(const float4*)Aptr;  Aptr += astep;
        float4 bv = *(const float4*)Bptr;  Bptr += bstep;
        if (TA) {
            As[0][(tseg + 0) * SPAD + trow] = av.x;
            As[0][(tseg + 1) * SPAD + trow] = av.y;
            As[0][(tseg + 2) * SPAD + trow] = av.z;
            As[0][(tseg + 3) * SPAD + trow] = av.w;
        } else {
            *(float4*)&As[0][drow * SPAD + dcol] = av;
        }
        if (TB) {
            Bs[0][(tseg + 0) * SPAD + trow] = bv.x;
            Bs[0][(tseg + 1) * SPAD + trow] = bv.y;
            Bs[0][(tseg + 2) * SPAD + trow] = bv.z;
            Bs[0][(tseg + 3) * SPAD + trow] = bv.w;
        } else {
            *(float4*)&Bs[0][drow * SPAD + dcol] = bv;
        }
    }
    __syncthreads();

    int buf = 0;
    for (int k0 = 0; k0 < Ktot; k0 += 8) {
        const bool has_next = (k0 + 8) < Ktot;
        float4 av, bv;
        if (has_next) {                       // issue next global loads early
            av = *(const float4*)Aptr;  Aptr += astep;
            bv = *(const float4*)Bptr;  Bptr += bstep;
        }

        const float* __restrict__ Asb = As[buf];
        const float* __restrict__ Bsb = Bs[buf];
        #pragma unroll
        for (int k = 0; k < 8; k++) {
            float a[8], b[8];
            *(float4*)&a[0] = *(const float4*)&Asb[k * SPAD + ty * 4];
            *(float4*)&a[4] = *(const float4*)&Asb[k * SPAD + 64 + ty * 4];
            *(float4*)&b[0] = *(const float4*)&Bsb[k * SPAD + tx * 4];
            *(float4*)&b[4] = *(const float4*)&Bsb[k * SPAD + 64 + tx * 4];
            #pragma unroll
            for (int mi = 0; mi < 8; mi++)
                #pragma unroll
                for (int ni = 0; ni < 8; ni++)
                    acc[mi][ni] = fmaf(a[mi], b[ni], acc[mi][ni]);
        }

        if (has_next) {
            const int nb = buf ^ 1;
            if (TA) {
                As[nb][(tseg + 0) * SPAD + trow] = av.x;
                As[nb][(tseg + 1) * SPAD + trow] = av.y;
                As[nb][(tseg + 2) * SPAD + trow] = av.z;
                As[nb][(tseg + 3) * SPAD + trow] = av.w;
            } else {
                *(float4*)&As[nb][drow * SPAD + dcol] = av;
            }
            if (TB) {
                Bs[nb][(tseg + 0) * SPAD + trow] = bv.x;
                Bs[nb][(tseg + 1) * SPAD + trow] = bv.y;
                Bs[nb][(tseg + 2) * SPAD + trow] = bv.z;
                Bs[nb][(tseg + 3) * SPAD + trow] = bv.w;
            } else {
                *(float4*)&Bs[nb][drow * SPAD + dcol] = bv;
            }
            __syncthreads();
            buf = nb;
        }
    }

    // epilogue: two 4-row halves x two 4-col halves, float4 stores
    #pragma unroll
    for (int hm = 0; hm < 2; hm++) {
        #pragma unroll
        for (int j = 0; j < 4; j++) {
            const int m = m0 + hm * 64 + ty * 4 + j;
            #pragma unroll
            for (int hn = 0; hn < 2; hn++) {
                const int n = n0 + hn * 64 + tx * 4;
                float4 v;
                v.x = acc[hm * 4 + j][hn * 4 + 0];
                v.y = acc[hm * 4 + j][hn * 4 + 1];
                v.z = acc[hm * 4 + j][hn * 4 + 2];
                v.w = acc[hm * 4 + j][hn * 4 + 3];
                if (BIAS) {
                    v.x += bias[n + 0];
                    v.y += bias[n + 1];
                    v.z += bias[n + 2];
                    v.w += bias[n + 3];
                }
                *(float4*)&C[(size_t)m * ldc + n] = v;
            }
        }
    }
}

// ---------------------------------------------------------------------------
// Column-wise softmax over p on attnT[b][p][i]  (softmax axis = p = rows).
// Block = (32 columns) x (8 p-slices). Each thread owns 288 rows of one
// column; partial (max,sum) pairs combined in shared memory. 576 CTAs total
// (vs 72 before) -> latency hiding instead of 0.5 CTA/SM.
// ---------------------------------------------------------------------------
__global__ void __launch_bounds__(256) softmax_kernel(float* __restrict__ attn)
{
    __shared__ float sm[8][33];
    __shared__ float ss[8][33];

    const int b  = blockIdx.y;
    const int tx = threadIdx.x;              // 0..31, column within tile
    const int ty = threadIdx.y;              // 0..7, p-slice
    const int i  = blockIdx.x * 32 + tx;
    float* col = attn + (size_t)b * NP * NP + i;

    float m = -3.402823466e38f;
    float s = 0.f;
    #pragma unroll 4
    for (int p = ty; p < NP; p += 8) {
        const float x = col[(size_t)p * NP];
        const float mn = fmaxf(m, x);
        s = s * __expf(m - mn) + __expf(x - mn);
        m = mn;
    }
    sm[ty][tx] = m;
    ss[ty][tx] = s;
    __syncthreads();

    if (ty == 0) {
        float M = sm[0][tx], S = ss[0][tx];
        #pragma unroll
        for (int y = 1; y < 8; y++) {
            const float m2 = sm[y][tx], s2 = ss[y][tx];
            const float Mn = fmaxf(M, m2);
            S = S * __expf(M - Mn) + s2 * __expf(m2 - Mn);
            M = Mn;
        }
        sm[0][tx] = M;
        ss[0][tx] = 1.0f / S;
    }
    __syncthreads();

    const float M   = sm[0][tx];
    const float inv = ss[0][tx];
    #pragma unroll 4
    for (int p = ty; p < NP; p += 8) {
        const float x = col[(size_t)p * NP];
        col[(size_t)p * NP] = __expf(x - M) * inv;
    }
}

// ---------------------------------------------------------------------------
extern "C" void kernel_launch(void* const* d_in, const int* in_sizes, int n_in,
                              void* d_out, int out_size)
{
    const float* qf = (const float*)d_in[0];   // [B, CQ, 48, 48]
    const float* rf = (const float*)d_in[1];   // [B, CR, 48, 48]
    const float* Wq = (const float*)d_in[2];   // [HID, CQ]
    const float* bq = (const float*)d_in[3];   // [HID]
    const float* Wk = (const float*)d_in[4];   // [HID, CR]
    const float* bk = (const float*)d_in[5];   // [HID]
    float* out = (float*)d_out;                // [B, CR, 48, 48]

    float *Qp, *Kp, *Ap;
    cudaGetSymbolAddress((void**)&Qp, g_Q);
    cudaGetSymbolAddress((void**)&Kp, g_K);
    cudaGetSymbolAddress((void**)&Ap, g_attn);

    // 1) Q = Wq * qf + bq   -> g_Q[b][i][k]
    gemm128<false, true, true><<<dim3(NP / 128, HID / 128, BB), 256>>>(
        qf, NP, (size_t)CQ * NP,
        Wq, CQ, 0,
        bq,
        Qp, HID, (size_t)NP * HID,
        CQ);

    // 2) K = Wk * rf + bk   -> g_K[b][p][k]
    gemm128<false, true, true><<<dim3(NP / 128, HID / 128, BB), 256>>>(
        rf, NP, (size_t)CR * NP,
        Wk, CR, 0,
        bk,
        Kp, HID, (size_t)NP * HID,
        CR);

    // 3) logits (transposed): attnT[p][i] = sum_k K[p][k] * Q[i][k]
    gemm128<true, true, false><<<dim3(NP / 128, NP / 128, BB), 256>>>(
        Kp, HID, (size_t)NP * HID,
        Qp, HID, (size_t)NP * HID,
        nullptr,
        Ap, NP, (size_t)NP * NP,
        HID);

    // 4) softmax over p (rows of attnT), per query pixel i
    softmax_kernel<<<dim3(NP / 32, BB), dim3(32, 8)>>>(Ap);

    // 5) attended: out[c][i] = sum_p rf[c][p] * attnT[p][i]
    gemm128<true, false, false><<<dim3(CR / 128, NP / 128, BB), 256>>>(
        rf, NP, (size_t)CR * NP,
        Ap, NP, (size_t)NP * NP,
        nullptr,
        out, NP, (size_t)CR * NP,
        NP);
}

// round 4
// speedup vs baseline: 1.4205x; 1.1944x over previous
#include <cuda_runtime.h>
#include <cuda_bf16.h>
#include <math.h>
#include <stdint.h>

// Problem constants
#define BB   8
#define CQ   1024
#define CR   512
#define HID  256
#define NP   2304          // H*W = 48*48

#define KC   16            // k per smem stage
#define PS   20            // smem words per row: 8 hi-pair + 8 lo-pair + 4 pad

// ---------------------------------------------------------------------------
// Device-global scratch (no allocations allowed). All "planes" are bf16
// hi/lo pairs stored as u32 arrays (two bf16 per word, even k in low half).
// ---------------------------------------------------------------------------
__device__ uint32_t g_qfT_hi[(size_t)BB * NP * CQ / 2];   // [b][i][c]
__device__ uint32_t g_qfT_lo[(size_t)BB * NP * CQ / 2];
__device__ uint32_t g_rfT_hi[(size_t)BB * NP * CR / 2];   // [b][p][c]
__device__ uint32_t g_rfT_lo[(size_t)BB * NP * CR / 2];
__device__ uint32_t g_rfS_hi[(size_t)BB * CR * NP / 2];   // [b][c][p]
__device__ uint32_t g_rfS_lo[(size_t)BB * CR * NP / 2];
__device__ uint32_t g_Wq_hi[(size_t)HID * CQ / 2];
__device__ uint32_t g_Wq_lo[(size_t)HID * CQ / 2];
__device__ uint32_t g_Wk_hi[(size_t)HID * CR / 2];
__device__ uint32_t g_Wk_lo[(size_t)HID * CR / 2];
__device__ uint32_t g_Q_hi[(size_t)BB * NP * HID / 2];    // [b][i][o]
__device__ uint32_t g_Q_lo[(size_t)BB * NP * HID / 2];
__device__ uint32_t g_K_hi[(size_t)BB * NP * HID / 2];    // [b][p][o]
__device__ uint32_t g_K_lo[(size_t)BB * NP * HID / 2];
__device__ float    g_attn[(size_t)BB * NP * NP];         // [b][p][i] fp32 logits
__device__ uint32_t g_at2_hi[(size_t)BB * NP * NP / 2];   // [b][i][p]
__device__ uint32_t g_at2_lo[(size_t)BB * NP * NP / 2];

// ---------------------------------------------------------------------------
// helpers
// ---------------------------------------------------------------------------
__device__ __forceinline__ void split_bf16(float x, unsigned short &h, unsigned short &l) {
    __nv_bfloat16 hb = __float2bfloat16_rn(x);
    h = __bfloat16_as_ushort(hb);
    float r = x - __bfloat162float(hb);
    l = __bfloat16_as_ushort(__float2bfloat16_rn(r));
}
__device__ __forceinline__ void split_pair_words(float x0, float x1,
                                                 uint32_t &hw, uint32_t &lw) {
    unsigned short h0, l0, h1, l1;
    split_bf16(x0, h0, l0);
    split_bf16(x1, h1, l1);
    hw = (uint32_t)h0 | ((uint32_t)h1 << 16);
    lw = (uint32_t)l0 | ((uint32_t)l1 << 16);
}

__device__ __forceinline__ void mma_bf16(float c[4], const uint32_t a[4],
                                         const uint32_t b[2]) {
    asm volatile(
        "mma.sync.aligned.m16n8k16.row.col.f32.bf16.bf16.f32 "
        "{%0,%1,%2,%3}, {%4,%5,%6,%7}, {%8,%9}, {%0,%1,%2,%3};\n"
        : "+f"(c[0]), "+f"(c[1]), "+f"(c[2]), "+f"(c[3])
        : "r"(a[0]), "r"(a[1]), "r"(a[2]), "r"(a[3]),
          "r"(b[0]), "r"(b[1]));
}

// ---------------------------------------------------------------------------
// Elementwise split: fp32 -> hi/lo bf16 planes (pairs packed in u32).
// ---------------------------------------------------------------------------
__global__ void __launch_bounds__(256) split_pairs(
    const float* __restrict__ src,
    uint32_t* __restrict__ dhi, uint32_t* __restrict__ dlo, size_t npairs)
{
    size_t i = (size_t)blockIdx.x * 256 + threadIdx.x;
    if (i >= npairs) return;
    float x0 = src[2 * i], x1 = src[2 * i + 1];
    uint32_t hw, lw;
    split_pair_words(x0, x1, hw, lw);
    dhi[i] = hw;
    dlo[i] = lw;
}

// ---------------------------------------------------------------------------
// Tiled transpose + split: src fp32 [R][C] -> dst hi/lo bf16 [C][R].
// grid (C/32, R/64, B), block (32, 8). Reads and writes fully coalesced.
// ---------------------------------------------------------------------------
__global__ void __launch_bounds__(256) transpose_split(
    const float* __restrict__ src,
    uint32_t* __restrict__ dhi, uint32_t* __restrict__ dlo,
    int R, int C)
{
    __shared__ float s[64][33];
    const int b = blockIdx.z;
    src += (size_t)b * R * C;
    const size_t dbatch = (size_t)C * (R >> 1);
    dhi += (size_t)b * dbatch;
    dlo += (size_t)b * dbatch;

    const int c0 = blockIdx.x * 32;
    const int r0 = blockIdx.y * 64;
    const int tx = threadIdx.x, ty = threadIdx.y;

    #pragma unroll
    for (int j = 0; j < 8; j++) {
        const int r = ty + 8 * j;
        s[r][tx] = src[(size_t)(r0 + r) * C + c0 + tx];
    }
    __syncthreads();

    #pragma unroll
    for (int j = 0; j < 4; j++) {
        const int cl = ty + 8 * j;
        const float x0 = s[2 * tx][cl];
        const float x1 = s[2 * tx + 1][cl];
        uint32_t hw, lw;
        split_pair_words(x0, x1, hw, lw);
        const size_t o = (size_t)(c0 + cl) * (R >> 1) + (r0 >> 1) + tx;
        dhi[o] = hw;
        dlo[o] = lw;
    }
}

// ---------------------------------------------------------------------------
// Uniform split-bf16 tensor-core GEMM.
//   C[m][n] = sum_k A[m][k] * B[n][k]  (both operands R-layout hi/lo planes)
// 128x128 CTA tile, 256 threads, 8 warps = 2(m) x 4(n), warp tile 64x32,
// m16n8k16 atoms, 3 MMAs per atom (ah*bh + ah*bl + al*bh), fp32 accumulate.
// OSPLIT: write hi/lo bf16 planes; else fp32.
// ---------------------------------------------------------------------------
template<bool BIAS, bool OSPLIT>
__global__ void __launch_bounds__(256) bgemm(
    const uint32_t* __restrict__ Ahi32, const uint32_t* __restrict__ Alo32,
    int lda, size_t sA,
    const uint32_t* __restrict__ Bhi32, const uint32_t* __restrict__ Blo32,
    int ldb, size_t sB,
    const float* __restrict__ bias,
    float* __restrict__ C, uint32_t* __restrict__ Chi, uint32_t* __restrict__ Clo,
    int ldc, size_t sC, int Ktot)
{
    __shared__ uint32_t As[2][128 * PS];
    __shared__ uint32_t Bs[2][128 * PS];

    const int bz = blockIdx.z;
    const __nv_bfloat16* Ahi = (const __nv_bfloat16*)Ahi32 + sA * bz;
    const __nv_bfloat16* Alo = (const __nv_bfloat16*)Alo32 + sA * bz;
    const __nv_bfloat16* Bhi = (const __nv_bfloat16*)Bhi32 + sB * bz;
    const __nv_bfloat16* Blo = (const __nv_bfloat16*)Blo32 + sB * bz;

    const int tid = threadIdx.x;
    const int m0  = blockIdx.x * 128;
    const int n0  = blockIdx.y * 128;

    // loader: thread -> (row, plane)
    const int lrow = tid >> 1;
    const int lpl  = tid & 1;
    const __nv_bfloat16* Asrc = (lpl ? Alo : Ahi) + (size_t)(m0 + lrow) * lda;
    const __nv_bfloat16* Bsrc = (lpl ? Blo : Bhi) + (size_t)(n0 + lrow) * ldb;
    const uint32_t sbase = lrow * PS + lpl * 8;

    // warp/lane decomposition
    const int wid = tid >> 5, lane = tid & 31;
    const int wm = (wid & 1) * 64;
    const int wn = (wid >> 1) * 32;
    const int qr = lane >> 2, qc = lane & 3;

    int arow[4], brow[4];
    #pragma unroll
    for (int mt = 0; mt < 4; mt++) arow[mt] = (wm + mt * 16 + qr) * PS;
    #pragma unroll
    for (int nt = 0; nt < 4; nt++) brow[nt] = (wn + nt * 8 + qr) * PS;

    float acc[4][4][4];
    #pragma unroll
    for (int mt = 0; mt < 4; mt++)
        #pragma unroll
        for (int nt = 0; nt < 4; nt++)
            #pragma unroll
            for (int r = 0; r < 4; r++) acc[mt][nt][r] = 0.f;

    // ---- prologue: stage 0 ----
    uint4 sa0 = *(const uint4*)(Asrc);
    uint4 sa1 = *(const uint4*)(Asrc + 8);
    uint4 sb0 = *(const uint4*)(Bsrc);
    uint4 sb1 = *(const uint4*)(Bsrc + 8);
    *(uint4*)&As[0][sbase]     = sa0;
    *(uint4*)&As[0][sbase + 4] = sa1;
    *(uint4*)&Bs[0][sbase]     = sb0;
    *(uint4*)&Bs[0][sbase + 4] = sb1;
    __syncthreads();

    const int nk = Ktot / KC;
    int buf = 0;
    for (int kb = 0; kb < nk; kb++) {
        const bool has_next = (kb + 1) < nk;
        if (has_next) {
            const int k0 = (kb + 1) * KC;
            sa0 = *(const uint4*)(Asrc + k0);
            sa1 = *(const uint4*)(Asrc + k0 + 8);
            sb0 = *(const uint4*)(Bsrc + k0);
            sb1 = *(const uint4*)(Bsrc + k0 + 8);
        }

        const uint32_t* __restrict__ Ab = As[buf];
        const uint32_t* __restrict__ Bb = Bs[buf];

        uint32_t ah[4][4], al[4][4], bh[4][2], bl[4][2];
        #pragma unroll
        for (int mt = 0; mt < 4; mt++) {
            const int r = arow[mt];
            ah[mt][0] = Ab[r + qc];
            ah[mt][1] = Ab[r + 8 * PS + qc];
            ah[mt][2] = Ab[r + 4 + qc];
            ah[mt][3] = Ab[r + 8 * PS + 4 + qc];
            al[mt][0] = Ab[r + 8 + qc];
            al[mt][1] = Ab[r + 8 * PS + 8 + qc];
            al[mt][2] = Ab[r + 12 + qc];
            al[mt][3] = Ab[r + 8 * PS + 12 + qc];
        }
        #pragma unroll
        for (int nt = 0; nt < 4; nt++) {
            const int r = brow[nt];
            bh[nt][0] = Bb[r + qc];
            bh[nt][1] = Bb[r + 4 + qc];
            bl[nt][0] = Bb[r + 8 + qc];
            bl[nt][1] = Bb[r + 12 + qc];
        }

        #pragma unroll
        for (int mt = 0; mt < 4; mt++)
            #pragma unroll
            for (int nt = 0; nt < 4; nt++) {
                mma_bf16(acc[mt][nt], ah[mt], bl[nt]);
                mma_bf16(acc[mt][nt], al[mt], bh[nt]);
                mma_bf16(acc[mt][nt], ah[mt], bh[nt]);
            }

        if (has_next) {
            const int nb = buf ^ 1;
            __syncthreads();                 // prior-stage reads done before overwrite
            *(uint4*)&As[nb][sbase]     = sa0;
            *(uint4*)&As[nb][sbase + 4] = sa1;
            *(uint4*)&Bs[nb][sbase]     = sb0;
            *(uint4*)&Bs[nb][sbase + 4] = sb1;
            __syncthreads();
            buf = nb;
        }
    }

    // ---- epilogue ----
    #pragma unroll
    for (int mt = 0; mt < 4; mt++) {
        #pragma unroll
        for (int nt = 0; nt < 4; nt++) {
            const int row = m0 + wm + mt * 16 + qr;
            const int col = n0 + wn + nt * 8 + 2 * qc;
            float v0 = acc[mt][nt][0], v1 = acc[mt][nt][1];
            float v2 = acc[mt][nt][2], v3 = acc[mt][nt][3];
            if (BIAS) {
                const float b0 = bias[col], b1 = bias[col + 1];
                v0 += b0; v1 += b1; v2 += b0; v3 += b1;
            }
            if (OSPLIT) {
                uint32_t* chb = Chi + (size_t)bz * (sC >> 1);
                uint32_t* clb = Clo + (size_t)bz * (sC >> 1);
                uint32_t hw, lw;
                split_pair_words(v0, v1, hw, lw);
                size_t o = (size_t)row * (ldc >> 1) + (col >> 1);
                chb[o] = hw; clb[o] = lw;
                split_pair_words(v2, v3, hw, lw);
                o = (size_t)(row + 8) * (ldc >> 1) + (col >> 1);
                chb[o] = hw; clb[o] = lw;
            } else {
                float* cb = C + sC * bz;
                *(float2*)&cb[(size_t)row * ldc + col]       = make_float2(v0, v1);
                *(float2*)&cb[(size_t)(row + 8) * ldc + col] = make_float2(v2, v3);
            }
        }
    }
}

// ---------------------------------------------------------------------------
// Column-wise softmax over p on attnT[b][p][i] (fp32, in place).
// ---------------------------------------------------------------------------
__global__ void __launch_bounds__(256) softmax_kernel(float* __restrict__ attn)
{
    __shared__ float sm[8][33];
    __shared__ float ss[8][33];

    const int b  = blockIdx.y;
    const int tx = threadIdx.x;
    const int ty = threadIdx.y;
    const int i  = blockIdx.x * 32 + tx;
    float* col = attn + (size_t)b * NP * NP + i;

    float m = -3.402823466e38f;
    float s = 0.f;
    #pragma unroll 4
    for (int p = ty; p < NP; p += 8) {
        const float x = col[(size_t)p * NP];
        const float mn = fmaxf(m, x);
        s = s * __expf(m - mn) + __expf(x - mn);
        m = mn;
    }
    sm[ty][tx] = m;
    ss[ty][tx] = s;
    __syncthreads();

    if (ty == 0) {
        float M = sm[0][tx], S = ss[0][tx];
        #pragma unroll
        for (int y = 1; y < 8; y++) {
            const float m2 = sm[y][tx], s2 = ss[y][tx];
            const float Mn = fmaxf(M, m2);
            S = S * __expf(M - Mn) + s2 * __expf(m2 - Mn);
            M = Mn;
        }
        sm[0][tx] = M;
        ss[0][tx] = 1.0f / S;
    }
    __syncthreads();

    const float M   = sm[0][tx];
    const float inv = ss[0][tx];
    #pragma unroll 4
    for (int p = ty; p < NP; p += 8) {
        const float x = col[(size_t)p * NP];
        col[(size_t)p * NP] = __expf(x - M) * inv;
    }
}

// ---------------------------------------------------------------------------
extern "C" void kernel_launch(void* const* d_in, const int* in_sizes, int n_in,
                              void* d_out, int out_size)
{
    const float* qf = (const float*)d_in[0];   // [B, CQ, 48, 48]
    const float* rf = (const float*)d_in[1];   // [B, CR, 48, 48]
    const float* Wq = (const float*)d_in[2];   // [HID, CQ]
    const float* bq = (const float*)d_in[3];   // [HID]
    const float* Wk = (const float*)d_in[4];   // [HID, CR]
    const float* bk = (const float*)d_in[5];   // [HID]
    float* out = (float*)d_out;                // [B, CR, 48, 48]

    uint32_t *qfTh, *qfTl, *rfTh, *rfTl, *rfSh, *rfSl;
    uint32_t *Wqh, *Wql, *Wkh, *Wkl, *Qh, *Ql, *Kh, *Kl, *a2h, *a2l;
    float *Ap;
    cudaGetSymbolAddress((void**)&qfTh, g_qfT_hi);
    cudaGetSymbolAddress((void**)&qfTl, g_qfT_lo);
    cudaGetSymbolAddress((void**)&rfTh, g_rfT_hi);
    cudaGetSymbolAddress((void**)&rfTl, g_rfT_lo);
    cudaGetSymbolAddress((void**)&rfSh, g_rfS_hi);
    cudaGetSymbolAddress((void**)&rfSl, g_rfS_lo);
    cudaGetSymbolAddress((void**)&Wqh, g_Wq_hi);
    cudaGetSymbolAddress((void**)&Wql, g_Wq_lo);
    cudaGetSymbolAddress((void**)&Wkh, g_Wk_hi);
    cudaGetSymbolAddress((void**)&Wkl, g_Wk_lo);
    cudaGetSymbolAddress((void**)&Qh, g_Q_hi);
    cudaGetSymbolAddress((void**)&Ql, g_Q_lo);
    cudaGetSymbolAddress((void**)&Kh, g_K_hi);
    cudaGetSymbolAddress((void**)&Kl, g_K_lo);
    cudaGetSymbolAddress((void**)&a2h, g_at2_hi);
    cudaGetSymbolAddress((void**)&a2l, g_at2_lo);
    cudaGetSymbolAddress((void**)&Ap, g_attn);

    // ---- prepass: splits + transposes ----
    {
        size_t np;
        np = (size_t)HID * CQ / 2;
        split_pairs<<<(unsigned)((np + 255) / 256), 256>>>(Wq, Wqh, Wql, np);
        np = (size_t)HID * CR / 2;
        split_pairs<<<(unsigned)((np + 255) / 256), 256>>>(Wk, Wkh, Wkl, np);
        np = (size_t)BB * CR * NP / 2;
        split_pairs<<<(unsigned)((np + 255) / 256), 256>>>(rf, rfSh, rfSl, np);
    }
    transpose_split<<<dim3(NP / 32, CQ / 64, BB), dim3(32, 8)>>>(qf, qfTh, qfTl, CQ, NP);
    transpose_split<<<dim3(NP / 32, CR / 64, BB), dim3(32, 8)>>>(rf, rfTh, rfTl, CR, NP);

    // ---- GEMM1: Q[i][o] = qfT[i][c] * Wq[o][c] + bq -> hi/lo planes ----
    bgemm<true, true><<<dim3(NP / 128, HID / 128, BB), 256>>>(
        qfTh, qfTl, CQ, (size_t)NP * CQ,
        Wqh, Wql, CQ, 0,
        bq,
        nullptr, Qh, Ql, HID, (size_t)NP * HID,
        CQ);

    // ---- GEMM2: K[p][o] = rfT[p][c] * Wk[o][c] + bk -> hi/lo planes ----
    bgemm<true, true><<<dim3(NP / 128, HID / 128, BB), 256>>>(
        rfTh, rfTl, CR, (size_t)NP * CR,
        Wkh, Wkl, CR, 0,
        bk,
        nullptr, Kh, Kl, HID, (size_t)NP * HID,
        CR);

    // ---- GEMM3: attnT[p][i] = K[p][k] * Q[i][k] (fp32 out) ----
    bgemm<false, false><<<dim3(NP / 128, NP / 128, BB), 256>>>(
        Kh, Kl, HID, (size_t)NP * HID,
        Qh, Ql, HID, (size_t)NP * HID,
        nullptr,
        Ap, nullptr, nullptr, NP, (size_t)NP * NP,
        HID);

    // ---- softmax over p ----
    softmax_kernel<<<dim3(NP / 32, BB), dim3(32, 8)>>>(Ap);

    // ---- attnT[p][i] -> attn2[i][p] hi/lo planes ----
    transpose_split<<<dim3(NP / 32, NP / 64, BB), dim3(32, 8)>>>(Ap, a2h, a2l, NP, NP);

    // ---- GEMM4: out[c][i] = rfS[c][p] * attn2[i][p] (fp32 out) ----
    bgemm<false, false><<<dim3(CR / 128, NP / 128, BB), 256>>>(
        rfSh, rfSl, NP, (size_t)CR * NP,
        a2h, a2l, NP, (size_t)NP * NP,
        nullptr,
        out, nullptr, nullptr, NP, (size_t)CR * NP,
        NP);
}

// round 5
// speedup vs baseline: 1.7849x; 1.2566x over previous
#include <cuda_runtime.h>
#include <cuda_bf16.h>
#include <math.h>
#include <stdint.h>

// Problem constants
#define BB   8
#define CQ   1024
#define CR   512
#define HID  256
#define NP   2304          // H*W = 48*48

#define KC   16            // k per smem stage
#define PS   20            // smem words per row: 8 hi-pair + 8 lo-pair + 4 pad

// ---------------------------------------------------------------------------
// Device-global scratch. All "planes" are bf16 hi/lo pairs packed in u32.
// ---------------------------------------------------------------------------
__device__ uint32_t g_qfT_hi[(size_t)BB * NP * CQ / 2];   // [b][i][c]
__device__ uint32_t g_qfT_lo[(size_t)BB * NP * CQ / 2];
__device__ uint32_t g_rfT_hi[(size_t)BB * NP * CR / 2];   // [b][p][c]
__device__ uint32_t g_rfT_lo[(size_t)BB * NP * CR / 2];
__device__ uint32_t g_rfS_hi[(size_t)BB * CR * NP / 2];   // [b][c][p]
__device__ uint32_t g_rfS_lo[(size_t)BB * CR * NP / 2];
__device__ uint32_t g_Wq_hi[(size_t)HID * CQ / 2];
__device__ uint32_t g_Wq_lo[(size_t)HID * CQ / 2];
__device__ uint32_t g_Wk_hi[(size_t)HID * CR / 2];
__device__ uint32_t g_Wk_lo[(size_t)HID * CR / 2];
__device__ uint32_t g_Q_hi[(size_t)BB * NP * HID / 2];    // [b][i][o]
__device__ uint32_t g_Q_lo[(size_t)BB * NP * HID / 2];
__device__ uint32_t g_K_hi[(size_t)BB * NP * HID / 2];    // [b][p][o]
__device__ uint32_t g_K_lo[(size_t)BB * NP * HID / 2];
__device__ float    g_attn[(size_t)BB * NP * NP];         // [b][p][i] fp32 logits
__device__ uint32_t g_at2_hi[(size_t)BB * NP * NP / 2];   // [b][i][p]
__device__ uint32_t g_at2_lo[(size_t)BB * NP * NP / 2];

// ---------------------------------------------------------------------------
// helpers
// ---------------------------------------------------------------------------
__device__ __forceinline__ void split_bf16(float x, unsigned short &h, unsigned short &l) {
    __nv_bfloat16 hb = __float2bfloat16_rn(x);
    h = __bfloat16_as_ushort(hb);
    float r = x - __bfloat162float(hb);
    l = __bfloat16_as_ushort(__float2bfloat16_rn(r));
}
__device__ __forceinline__ void split_pair_words(float x0, float x1,
                                                 uint32_t &hw, uint32_t &lw) {
    unsigned short h0, l0, h1, l1;
    split_bf16(x0, h0, l0);
    split_bf16(x1, h1, l1);
    hw = (uint32_t)h0 | ((uint32_t)h1 << 16);
    lw = (uint32_t)l0 | ((uint32_t)l1 << 16);
}

__device__ __forceinline__ void mma_bf16(float c[4], const uint32_t a[4],
                                         const uint32_t b0, const uint32_t b1) {
    asm volatile(
        "mma.sync.aligned.m16n8k16.row.col.f32.bf16.bf16.f32 "
        "{%0,%1,%2,%3}, {%4,%5,%6,%7}, {%8,%9}, {%0,%1,%2,%3};\n"
        : "+f"(c[0]), "+f"(c[1]), "+f"(c[2]), "+f"(c[3])
        : "r"(a[0]), "r"(a[1]), "r"(a[2]), "r"(a[3]),
          "r"(b0), "r"(b1));
}

__device__ __forceinline__ void ldsm4(uint32_t r[4], uint32_t addr) {
    asm volatile("ldmatrix.sync.aligned.m8n8.x4.shared.b16 {%0,%1,%2,%3}, [%4];"
                 : "=r"(r[0]), "=r"(r[1]), "=r"(r[2]), "=r"(r[3]) : "r"(addr));
}
__device__ __forceinline__ void cpasync16(uint32_t saddr, const void* g) {
    asm volatile("cp.async.cg.shared.global [%0], [%1], 16;" :: "r"(saddr), "l"(g));
}
#define CP_COMMIT() asm volatile("cp.async.commit_group;" ::: "memory")
#define CP_WAIT0()  asm volatile("cp.async.wait_group 0;" ::: "memory")

// ---------------------------------------------------------------------------
// Elementwise split: fp32 -> hi/lo bf16 planes (pairs packed in u32).
// ---------------------------------------------------------------------------
__global__ void __launch_bounds__(256) split_pairs(
    const float* __restrict__ src,
    uint32_t* __restrict__ dhi, uint32_t* __restrict__ dlo, size_t npairs)
{
    size_t i = (size_t)blockIdx.x * 256 + threadIdx.x;
    if (i >= npairs) return;
    float x0 = src[2 * i], x1 = src[2 * i + 1];
    uint32_t hw, lw;
    split_pair_words(x0, x1, hw, lw);
    dhi[i] = hw;
    dlo[i] = lw;
}

// ---------------------------------------------------------------------------
// Tiled transpose + split: src fp32 [R][C] -> dst hi/lo bf16 [C][R].
// ---------------------------------------------------------------------------
__global__ void __launch_bounds__(256) transpose_split(
    const float* __restrict__ src,
    uint32_t* __restrict__ dhi, uint32_t* __restrict__ dlo,
    int R, int C)
{
    __shared__ float s[64][33];
    const int b = blockIdx.z;
    src += (size_t)b * R * C;
    const size_t dbatch = (size_t)C * (R >> 1);
    dhi += (size_t)b * dbatch;
    dlo += (size_t)b * dbatch;

    const int c0 = blockIdx.x * 32;
    const int r0 = blockIdx.y * 64;
    const int tx = threadIdx.x, ty = threadIdx.y;

    #pragma unroll
    for (int j = 0; j < 8; j++) {
        const int r = ty + 8 * j;
        s[r][tx] = src[(size_t)(r0 + r) * C + c0 + tx];
    }
    __syncthreads();

    #pragma unroll
    for (int j = 0; j < 4; j++) {
        const int cl = ty + 8 * j;
        const float x0 = s[2 * tx][cl];
        const float x1 = s[2 * tx + 1][cl];
        uint32_t hw, lw;
        split_pair_words(x0, x1, hw, lw);
        const size_t o = (size_t)(c0 + cl) * (R >> 1) + (r0 >> 1) + tx;
        dhi[o] = hw;
        dlo[o] = lw;
    }
}

// ---------------------------------------------------------------------------
// Split-bf16 tensor-core GEMM, cp.async double buffer + ldmatrix fragments.
//   C[m][n] = sum_k A[m][k] * B[n][k]  (both operands R-layout hi/lo planes)
// 128x128 CTA tile, 256 threads, 8 warps = 2(m) x 4(n), warp tile 64x32,
// m16n8k16 atoms, 3 MMAs per atom (ah*bh + ah*bl + al*bh), fp32 accumulate.
// ---------------------------------------------------------------------------
template<bool BIAS, bool OSPLIT>
__global__ void __launch_bounds__(256, 2) bgemm(
    const uint32_t* __restrict__ Ahi32, const uint32_t* __restrict__ Alo32,
    int lda, size_t sA,
    const uint32_t* __restrict__ Bhi32, const uint32_t* __restrict__ Blo32,
    int ldb, size_t sB,
    const float* __restrict__ bias,
    float* __restrict__ C, uint32_t* __restrict__ Chi, uint32_t* __restrict__ Clo,
    int ldc, size_t sC, int Ktot)
{
    __shared__ uint32_t As[2][128 * PS];
    __shared__ uint32_t Bs[2][128 * PS];

    const int bz = blockIdx.z;
    const __nv_bfloat16* Ahi = (const __nv_bfloat16*)Ahi32 + sA * bz;
    const __nv_bfloat16* Alo = (const __nv_bfloat16*)Alo32 + sA * bz;
    const __nv_bfloat16* Bhi = (const __nv_bfloat16*)Bhi32 + sB * bz;
    const __nv_bfloat16* Blo = (const __nv_bfloat16*)Blo32 + sB * bz;

    const int tid = threadIdx.x;
    const int m0  = blockIdx.x * 128;
    const int n0  = blockIdx.y * 128;

    // cp.async loader: thread -> (row, plane); copies 2x16B per operand/stage
    const int lrow = tid >> 1;
    const int lpl  = tid & 1;
    const __nv_bfloat16* Asrc = (lpl ? Alo : Ahi) + (size_t)(m0 + lrow) * lda;
    const __nv_bfloat16* Bsrc = (lpl ? Blo : Bhi) + (size_t)(n0 + lrow) * ldb;
    const uint32_t sdst = (uint32_t)(lrow * PS + lpl * 8) * 4;   // bytes in stage

    const uint32_t aS = (uint32_t)__cvta_generic_to_shared(&As[0][0]);
    const uint32_t bS = (uint32_t)__cvta_generic_to_shared(&Bs[0][0]);
    const uint32_t stageB = 128 * PS * 4;

    // warp/lane decomposition
    const int wid = tid >> 5, lane = tid & 31;
    const int wm = (wid & 1) * 64;
    const int wn = (wid >> 1) * 32;
    const int qr = lane >> 2, qc = lane & 3;

    // ldmatrix per-lane addresses (byte offsets within a stage)
    // A tile mt: rows [wm+16mt, +16). lane -> row wm+16mt+(l&7)+(l&8), word (l&16)?4:0
    uint32_t aoff[4], boff[4];
    {
        const int arl = (lane & 7) + (lane & 8);
        const int awd = (lane & 16) ? 4 : 0;
        #pragma unroll
        for (int mt = 0; mt < 4; mt++)
            aoff[mt] = (uint32_t)(((wm + mt * 16 + arl) * PS + awd) * 4);
        // B tile nt: rows [wn+8nt, +8). lane -> row wn+8nt+(l&7), word ((l>>3)&3)*4
        const int brl = lane & 7;
        const int bwd = ((lane >> 3) & 3) * 4;
        #pragma unroll
        for (int nt = 0; nt < 4; nt++)
            boff[nt] = (uint32_t)(((wn + nt * 8 + brl) * PS + bwd) * 4);
    }

    float acc[4][4][4];
    #pragma unroll
    for (int mt = 0; mt < 4; mt++)
        #pragma unroll
        for (int nt = 0; nt < 4; nt++)
            #pragma unroll
            for (int r = 0; r < 4; r++) acc[mt][nt][r] = 0.f;

    // ---- prologue: stage 0 ----
    cpasync16(aS + sdst,      Asrc);
    cpasync16(aS + sdst + 16, Asrc + 8);
    cpasync16(bS + sdst,      Bsrc);
    cpasync16(bS + sdst + 16, Bsrc + 8);
    CP_COMMIT();
    CP_WAIT0();
    __syncthreads();

    const int nk = Ktot / KC;
    int buf = 0;
    for (int kb = 0; kb < nk; kb++) {
        const bool has_next = (kb + 1) < nk;
        if (has_next) {
            const int k0 = (kb + 1) * KC;
            const uint32_t ad = aS + (buf ^ 1) * stageB + sdst;
            const uint32_t bd = bS + (buf ^ 1) * stageB + sdst;
            cpasync16(ad,      Asrc + k0);
            cpasync16(ad + 16, Asrc + k0 + 8);
            cpasync16(bd,      Bsrc + k0);
            cpasync16(bd + 16, Bsrc + k0 + 8);
            CP_COMMIT();
        }

        const uint32_t ab = aS + buf * stageB;
        const uint32_t bb = bS + buf * stageB;

        uint32_t ah[4][4], al[4][4];
        #pragma unroll
        for (int mt = 0; mt < 4; mt++) {
            ldsm4(ah[mt], ab + aoff[mt]);          // hi plane (words 0..7)
            ldsm4(al[mt], ab + aoff[mt] + 32);     // lo plane (words 8..15)
        }
        #pragma unroll
        for (int nt = 0; nt < 4; nt++) {
            uint32_t bv[4];                        // {b0h, b1h, b0l, b1l}
            ldsm4(bv, bb + boff[nt]);
            #pragma unroll
            for (int mt = 0; mt < 4; mt++) {
                mma_bf16(acc[mt][nt], ah[mt], bv[2], bv[3]);   // ah*bl
                mma_bf16(acc[mt][nt], al[mt], bv[0], bv[1]);   // al*bh
                mma_bf16(acc[mt][nt], ah[mt], bv[0], bv[1]);   // ah*bh
            }
        }

        if (has_next) {
            CP_WAIT0();
            __syncthreads();
            buf ^= 1;
        }
    }

    // ---- epilogue ----
    #pragma unroll
    for (int mt = 0; mt < 4; mt++) {
        #pragma unroll
        for (int nt = 0; nt < 4; nt++) {
            const int row = m0 + wm + mt * 16 + qr;
            const int col = n0 + wn + nt * 8 + 2 * qc;
            float v0 = acc[mt][nt][0], v1 = acc[mt][nt][1];
            float v2 = acc[mt][nt][2], v3 = acc[mt][nt][3];
            if (BIAS) {
                const float b0 = bias[col], b1 = bias[col + 1];
                v0 += b0; v1 += b1; v2 += b0; v3 += b1;
            }
            if (OSPLIT) {
                uint32_t* chb = Chi + (size_t)bz * (sC >> 1);
                uint32_t* clb = Clo + (size_t)bz * (sC >> 1);
                uint32_t hw, lw;
                split_pair_words(v0, v1, hw, lw);
                size_t o = (size_t)row * (ldc >> 1) + (col >> 1);
                chb[o] = hw; clb[o] = lw;
                split_pair_words(v2, v3, hw, lw);
                o = (size_t)(row + 8) * (ldc >> 1) + (col >> 1);
                chb[o] = hw; clb[o] = lw;
            } else {
                float* cb = C + sC * bz;
                *(float2*)&cb[(size_t)row * ldc + col]       = make_float2(v0, v1);
                *(float2*)&cb[(size_t)(row + 8) * ldc + col] = make_float2(v2, v3);
            }
        }
    }
}

// ---------------------------------------------------------------------------
// Column-wise softmax over p on attnT[b][p][i] (fp32, in place).
// ---------------------------------------------------------------------------
__global__ void __launch_bounds__(256) softmax_kernel(float* __restrict__ attn)
{
    __shared__ float sm[8][33];
    __shared__ float ss[8][33];

    const int b  = blockIdx.y;
    const int tx = threadIdx.x;
    const int ty = threadIdx.y;
    const int i  = blockIdx.x * 32 + tx;
    float* col = attn + (size_t)b * NP * NP + i;

    float m = -3.402823466e38f;
    float s = 0.f;
    #pragma unroll 4
    for (int p = ty; p < NP; p += 8) {
        const float x = col[(size_t)p * NP];
        const float mn = fmaxf(m, x);
        s = s * __expf(m - mn) + __expf(x - mn);
        m = mn;
    }
    sm[ty][tx] = m;
    ss[ty][tx] = s;
    __syncthreads();

    if (ty == 0) {
        float M = sm[0][tx], S = ss[0][tx];
        #pragma unroll
        for (int y = 1; y < 8; y++) {
            const float m2 = sm[y][tx], s2 = ss[y][tx];
            const float Mn = fmaxf(M, m2);
            S = S * __expf(M - Mn) + s2 * __expf(m2 - Mn);
            M = Mn;
        }
        sm[0][tx] = M;
        ss[0][tx] = 1.0f / S;
    }
    __syncthreads();

    const float M   = sm[0][tx];
    const float inv = ss[0][tx];
    #pragma unroll 4
    for (int p = ty; p < NP; p += 8) {
        const float x = col[(size_t)p * NP];
        col[(size_t)p * NP] = __expf(x - M) * inv;
    }
}

// ---------------------------------------------------------------------------
extern "C" void kernel_launch(void* const* d_in, const int* in_sizes, int n_in,
                              void* d_out, int out_size)
{
    const float* qf = (const float*)d_in[0];   // [B, CQ, 48, 48]
    const float* rf = (const float*)d_in[1];   // [B, CR, 48, 48]
    const float* Wq = (const float*)d_in[2];   // [HID, CQ]
    const float* bq = (const float*)d_in[3];   // [HID]
    const float* Wk = (const float*)d_in[4];   // [HID, CR]
    const float* bk = (const float*)d_in[5];   // [HID]
    float* out = (float*)d_out;                // [B, CR, 48, 48]

    uint32_t *qfTh, *qfTl, *rfTh, *rfTl, *rfSh, *rfSl;
    uint32_t *Wqh, *Wql, *Wkh, *Wkl, *Qh, *Ql, *Kh, *Kl, *a2h, *a2l;
    float *Ap;
    cudaGetSymbolAddress((void**)&qfTh, g_qfT_hi);
    cudaGetSymbolAddress((void**)&qfTl, g_qfT_lo);
    cudaGetSymbolAddress((void**)&rfTh, g_rfT_hi);
    cudaGetSymbolAddress((void**)&rfTl, g_rfT_lo);
    cudaGetSymbolAddress((void**)&rfSh, g_rfS_hi);
    cudaGetSymbolAddress((void**)&rfSl, g_rfS_lo);
    cudaGetSymbolAddress((void**)&Wqh, g_Wq_hi);
    cudaGetSymbolAddress((void**)&Wql, g_Wq_lo);
    cudaGetSymbolAddress((void**)&Wkh, g_Wk_hi);
    cudaGetSymbolAddress((void**)&Wkl, g_Wk_lo);
    cudaGetSymbolAddress((void**)&Qh, g_Q_hi);
    cudaGetSymbolAddress((void**)&Ql, g_Q_lo);
    cudaGetSymbolAddress((void**)&Kh, g_K_hi);
    cudaGetSymbolAddress((void**)&Kl, g_K_lo);
    cudaGetSymbolAddress((void**)&a2h, g_at2_hi);
    cudaGetSymbolAddress((void**)&a2l, g_at2_lo);
    cudaGetSymbolAddress((void**)&Ap, g_attn);

    // ---- prepass: splits + transposes ----
    {
        size_t np;
        np = (size_t)HID * CQ / 2;
        split_pairs<<<(unsigned)((np + 255) / 256), 256>>>(Wq, Wqh, Wql, np);
        np = (size_t)HID * CR / 2;
        split_pairs<<<(unsigned)((np + 255) / 256), 256>>>(Wk, Wkh, Wkl, np);
        np = (size_t)BB * CR * NP / 2;
        split_pairs<<<(unsigned)((np + 255) / 256), 256>>>(rf, rfSh, rfSl, np);
    }
    transpose_split<<<dim3(NP / 32, CQ / 64, BB), dim3(32, 8)>>>(qf, qfTh, qfTl, CQ, NP);
    transpose_split<<<dim3(NP / 32, CR / 64, BB), dim3(32, 8)>>>(rf, rfTh, rfTl, CR, NP);

    // ---- GEMM1: Q[i][o] = qfT[i][c] * Wq[o][c] + bq -> hi/lo planes ----
    bgemm<true, true><<<dim3(NP / 128, HID / 128, BB), 256>>>(
        qfTh, qfTl, CQ, (size_t)NP * CQ,
        Wqh, Wql, CQ, 0,
        bq,
        nullptr, Qh, Ql, HID, (size_t)NP * HID,
        CQ);

    // ---- GEMM2: K[p][o] = rfT[p][c] * Wk[o][c] + bk -> hi/lo planes ----
    bgemm<true, true><<<dim3(NP / 128, HID / 128, BB), 256>>>(
        rfTh, rfTl, CR, (size_t)NP * CR,
        Wkh, Wkl, CR, 0,
        bk,
        nullptr, Kh, Kl, HID, (size_t)NP * HID,
        CR);

    // ---- GEMM3: attnT[p][i] = K[p][k] * Q[i][k] (fp32 out) ----
    bgemm<false, false><<<dim3(NP / 128, NP / 128, BB), 256>>>(
        Kh, Kl, HID, (size_t)NP * HID,
        Qh, Ql, HID, (size_t)NP * HID,
        nullptr,
        Ap, nullptr, nullptr, NP, (size_t)NP * NP,
        HID);

    // ---- softmax over p ----
    softmax_kernel<<<dim3(NP / 32, BB), dim3(32, 8)>>>(Ap);

    // ---- attnT[p][i] -> attn2[i][p] hi/lo planes ----
    transpose_split<<<dim3(NP / 32, NP / 64, BB), dim3(32, 8)>>>(Ap, a2h, a2l, NP, NP);

    // ---- GEMM4: out[c][i] = rfS[c][p] * attn2[i][p] (fp32 out) ----
    bgemm<false, false><<<dim3(CR / 128, NP / 128, BB), 256>>>(
        rfSh, rfSl, NP, (size_t)CR * NP,
        a2h, a2l, NP, (size_t)NP * NP,
        nullptr,
        out, nullptr, nullptr, NP, (size_t)CR * NP,
        NP);
}